// round 4
// baseline (speedup 1.0000x reference)
#include <cuda_runtime.h>
#include <math.h>
#include <stdint.h>

// Problem constants
constexpr int Lc    = 50;
constexpr int NSEQ  = 32 * 40;     // 1280 sequences
constexpr int NR    = NSEQ * Lc;   // 64000 (seq,time) rows
constexpr int H     = 128;
constexpr int G4    = 512;         // 4*H gates

// ---------------------------------------------------------------------------
// Device scratch
// ---------------------------------------------------------------------------
__device__ float g_X0[(size_t)NR * 64];
__device__ float g_Xa[(size_t)NR * 256];
__device__ float g_Xb[(size_t)NR * 256];
__device__ float g_xg[2][(size_t)NR * G4];
__device__ float g_agg[(size_t)NSEQ * 768];
__device__ float g_t1[(size_t)NSEQ * 512];
__device__ float g_t2[(size_t)NSEQ * 512];

// ---------------------------------------------------------------------------
// f32x2 helpers
// ---------------------------------------------------------------------------
__device__ __forceinline__ float2 ffma2(float2 a, float2 b, float2 c) {
    unsigned long long ud;
    asm("fma.rn.f32x2 %0, %1, %2, %3;"
        : "=l"(ud)
        : "l"(*(unsigned long long*)&a),
          "l"(*(unsigned long long*)&b),
          "l"(*(unsigned long long*)&c));
    float2 d; *(unsigned long long*)&d = ud; return d;
}
__device__ __forceinline__ float2 pack2(float lo, float hi) {
    float2 r; r.x = lo; r.y = hi; return r;
}
__device__ __forceinline__ float sigm_(float x) {
    return __fdividef(1.0f, 1.0f + __expf(-x));
}
__device__ __forceinline__ float tanh_(float x) {
    return __fdividef(2.0f, 1.0f + __expf(-2.0f * x)) - 1.0f;
}

// ---------------------------------------------------------------------------
// Kernel 1: input projection
// ---------------------------------------------------------------------------
__global__ __launch_bounds__(256) void inproj_kernel(
    const float* __restrict__ imu, const float* __restrict__ Win,
    const float* __restrict__ bin)
{
    int idx = blockIdx.x * 256 + threadIdx.x;
    int row = idx >> 6;
    int jj  = idx & 63;
    int l   = row % Lc;
    const float* xr = imu + (size_t)row * 6;
    float t    = (float)l * (1.0f / 49.0f);
    float rate = 1.0f;
    float acc = bin[jj];
#pragma unroll
    for (int k = 0; k < 6; k++) acc = fmaf(xr[k], Win[k * 64 + jj], acc);
    acc = fmaf(t,    Win[6 * 64 + jj], acc);
    acc = fmaf(rate, Win[7 * 64 + jj], acc);
    g_X0[(size_t)row * 64 + jj] = fmaxf(acc, 0.0f);
}

// ---------------------------------------------------------------------------
// Kernel 2: SGEMM + bias, f32x2, double-buffered smem (1 sync per k-tile)
// ---------------------------------------------------------------------------
__global__ __launch_bounds__(256) void sgemm_bias(
    const float* __restrict__ A, const float* __restrict__ B,
    float* __restrict__ C,
    const float* __restrict__ bias1, const float* __restrict__ bias2,
    int M, int N, int K,
    long long sB, long long sC, long long sBias)
{
    constexpr int BM = 128, BN = 128, BK = 8, TM = 8, TN = 8;
    __shared__ float As[2][BK][BM];
    __shared__ float Bs[2][BK][BN];

    const int dir = blockIdx.z;
    B += (size_t)dir * sB;
    C += (size_t)dir * sC;
    const float* b1 = bias1 + (size_t)dir * sBias;
    const float* b2 = bias2 ? bias2 + (size_t)dir * sBias : nullptr;
    const bool hasB2 = (b2 != nullptr);

    const int cRow = blockIdx.y, cCol = blockIdx.x;
    const int tid  = threadIdx.x;
    const int tCol = tid % (BN / TN);
    const int tRow = tid / (BN / TN);

    const int aRow = tid >> 1;
    const int aCol = (tid & 1) * 4;
    const int bRow = tid >> 5;
    const int bCol = (tid & 31) * 4;

    const float* Ab = A + (size_t)cRow * BM * K;
    const float* Bb = B + cCol * BN;

    float2 acc2[TM][TN / 2];
#pragma unroll
    for (int i = 0; i < TM; i++)
#pragma unroll
        for (int j = 0; j < TN / 2; j++) acc2[i][j] = pack2(0.f, 0.f);

    float regM[TM];
    const int niter = K / BK;

    // prologue: tile 0 into buffer 0
    {
        float4 av = *(const float4*)(Ab + (size_t)aRow * K + aCol);
        As[0][aCol + 0][aRow] = av.x;
        As[0][aCol + 1][aRow] = av.y;
        As[0][aCol + 2][aRow] = av.z;
        As[0][aCol + 3][aRow] = av.w;
        *(float4*)&Bs[0][bRow][bCol] =
            *(const float4*)(Bb + (size_t)bRow * N + bCol);
    }
    __syncthreads();

    for (int it = 0; it < niter; it++) {
        const int cur = it & 1, nxt = cur ^ 1;
        float4 av, bv;
        const bool more = (it + 1 < niter);
        if (more) {
            int k0 = (it + 1) * BK;
            av = *(const float4*)(Ab + (size_t)aRow * K + k0 + aCol);
            bv = *(const float4*)(Bb + (size_t)(k0 + bRow) * N + bCol);
        }
#pragma unroll
        for (int k = 0; k < BK; k++) {
            *(float4*)&regM[0] = *(const float4*)&As[cur][k][tRow * TM];
            *(float4*)&regM[4] = *(const float4*)&As[cur][k][tRow * TM + 4];
            float4 bn0 = *(const float4*)&Bs[cur][k][tCol * TN];
            float4 bn1 = *(const float4*)&Bs[cur][k][tCol * TN + 4];
            float2 n0 = pack2(bn0.x, bn0.y), n1 = pack2(bn0.z, bn0.w);
            float2 n2 = pack2(bn1.x, bn1.y), n3 = pack2(bn1.z, bn1.w);
#pragma unroll
            for (int i = 0; i < TM; i++) {
                float2 m2 = pack2(regM[i], regM[i]);
                acc2[i][0] = ffma2(m2, n0, acc2[i][0]);
                acc2[i][1] = ffma2(m2, n1, acc2[i][1]);
                acc2[i][2] = ffma2(m2, n2, acc2[i][2]);
                acc2[i][3] = ffma2(m2, n3, acc2[i][3]);
            }
        }
        if (more) {
            As[nxt][aCol + 0][aRow] = av.x;
            As[nxt][aCol + 1][aRow] = av.y;
            As[nxt][aCol + 2][aRow] = av.z;
            As[nxt][aCol + 3][aRow] = av.w;
            *(float4*)&Bs[nxt][bRow][bCol] = bv;
        }
        __syncthreads();
    }

#pragma unroll
    for (int i = 0; i < TM; i++) {
        size_t row = (size_t)cRow * BM + tRow * TM + i;
        float* Cr = C + row * N + cCol * BN + tCol * TN;
        const int colb = cCol * BN + tCol * TN;
#pragma unroll
        for (int j2 = 0; j2 < TN / 2; j2++) {
            float vx = acc2[i][j2].x + b1[colb + 2 * j2];
            float vy = acc2[i][j2].y + b1[colb + 2 * j2 + 1];
            if (hasB2) { vx += b2[colb + 2 * j2]; vy += b2[colb + 2 * j2 + 1]; }
            Cr[2 * j2]     = vx;
            Cr[2 * j2 + 1] = vy;
        }
    }
}

// ---------------------------------------------------------------------------
// Kernel 3: PERSISTENT BiLSTM layer, 2-CTA clusters with DSMEM h-exchange.
// 128 CTAs = 64 clusters. Cluster pair = same (dir, rowgroup), jt = rank.
// Each CTA: 40 rows x 64 hidden cols; Whh slice (128KB) in smem; c in regs.
// h published straight into BOTH CTAs' smem (local st + st.shared::cluster),
// synced with one barrier.cluster per step. hs double-buffered by parity.
// ---------------------------------------------------------------------------
__global__ __launch_bounds__(256) __cluster_dims__(2, 1, 1)
void lstm_layer(const float* __restrict__ Whh,
                const float* __restrict__ xgb,
                float* __restrict__ Xout)
{
    extern __shared__ float smem[];
    float4* ws  = (float4*)smem;                     // [128][64] gate quads
    float2* hs2 = (float2*)(smem + 128 * 64 * 4);    // [2][4*5*128] row-pair bufs
    constexpr int HBUF = 4 * 5 * 128;                // float2 per buffer

    const int bx   = blockIdx.x;
    const int jt   = bx & 1;                          // cluster rank
    const int dir  = bx >> 6;
    const int rgI  = (bx >> 1) & 31;
    const int row0 = rgI * 40;
    const int tid  = threadIdx.x;
    const int jj   = tid & 63;
    const int rg   = tid >> 6;
    const int col  = jt * 64 + jj;                    // hidden col within dir

    const float* W   = Whh + (size_t)dir * (H * G4);
    const float* xgd = xgb + (size_t)dir * NR * G4;

    // Stage Whh slice: ws[k][jj] = {W[k][col + g*128]}
    for (int idx = tid; idx < 128 * 64; idx += 256) {
        int k = idx >> 6, j = idx & 63;
        const float* wk = W + (size_t)k * G4 + jt * 64 + j;
        ws[idx] = make_float4(wk[0], wk[128], wk[256], wk[384]);
    }
    __syncthreads();

    // partner's hs2 base address (cluster DSMEM)
    uint32_t hs2_local;
    asm("{ .reg .u64 t; cvta.to.shared.u64 t, %1; cvt.u32.u64 %0, t; }"
        : "=r"(hs2_local) : "l"(hs2));
    uint32_t hs2_remote;
    asm("mapa.shared::cluster.u32 %0, %1, %2;"
        : "=r"(hs2_remote) : "r"(hs2_local), "r"(jt ^ 1));

    float c[10];
#pragma unroll
    for (int r = 0; r < 10; r++) c[r] = 0.0f;

    for (int step = 0; step < Lc; step++) {
        const int tin = dir ? (Lc - 1 - step) : step;

        // prefetch xg into accumulators (before waiting on partner)
        float2 acc[4][5];
#pragma unroll
        for (int p = 0; p < 5; p++) {
            int rowA = row0 + rg * 10 + 2 * p;
            const float* xa = xgd + ((size_t)rowA * Lc + tin) * G4 + col;
            const float* xb = xa + (size_t)Lc * G4;   // rowA+1
#pragma unroll
            for (int g = 0; g < 4; g++)
                acc[g][p] = pack2(xa[g * 128], xb[g * 128]);
        }

        if (step > 0) {
            asm volatile("barrier.cluster.wait.aligned;" ::: "memory");
            const float2* hrow = hs2 + (size_t)((step + 1) & 1) * HBUF
                                     + (size_t)rg * 5 * 128;
#pragma unroll 2
            for (int k = 0; k < 128; k++) {
                float4 w4 = ws[(size_t)k * 64 + jj];
                float2 w0 = pack2(w4.x, w4.x);
                float2 w1 = pack2(w4.y, w4.y);
                float2 w2 = pack2(w4.z, w4.z);
                float2 w3 = pack2(w4.w, w4.w);
#pragma unroll
                for (int p = 0; p < 5; p++) {
                    float2 h2 = hrow[(size_t)p * 128 + k];
                    acc[0][p] = ffma2(h2, w0, acc[0][p]);
                    acc[1][p] = ffma2(h2, w1, acc[1][p]);
                    acc[2][p] = ffma2(h2, w2, acc[2][p]);
                    acc[3][p] = ffma2(h2, w3, acc[3][p]);
                }
            }
        }

        // gates + state update + publish
        const int bufOff = (step & 1) * HBUF + rg * 5 * 128;
        float2* dstL = hs2 + bufOff;
        const uint32_t dstR = hs2_remote + (uint32_t)bufOff * 8u;
        const bool pub = (step < Lc - 1);
        float hval[10];
#pragma unroll
        for (int p = 0; p < 5; p++) {
            float i0 = sigm_(acc[0][p].x), i1 = sigm_(acc[0][p].y);
            float f0 = sigm_(acc[1][p].x), f1 = sigm_(acc[1][p].y);
            float ga = tanh_(acc[2][p].x), gb = tanh_(acc[2][p].y);
            float o0 = sigm_(acc[3][p].x), o1 = sigm_(acc[3][p].y);
            float c0 = fmaf(f0, c[2 * p],     i0 * ga);
            float c1 = fmaf(f1, c[2 * p + 1], i1 * gb);
            c[2 * p]     = c0;
            c[2 * p + 1] = c1;
            float h0 = o0 * tanh_(c0);
            float h1 = o1 * tanh_(c1);
            hval[2 * p] = h0; hval[2 * p + 1] = h1;
            if (pub) {
                float2 hp = pack2(h0, h1);
                dstL[p * 128 + col] = hp;
                asm volatile("st.shared::cluster.b64 [%0], %1;"
                             :: "r"(dstR + (uint32_t)(p * 128 + col) * 8u),
                                "l"(*(unsigned long long*)&hp)
                             : "memory");
            }
        }
        if (pub)
            asm volatile("barrier.cluster.arrive.aligned;" ::: "memory");

        // layer output (fire-and-forget)
#pragma unroll
        for (int r = 0; r < 10; r++) {
            int row = row0 + rg * 10 + r;
            Xout[((size_t)row * Lc + tin) * 256 + dir * H + col] = hval[r];
        }
    }
}

// ---------------------------------------------------------------------------
// Kernel 4: aggregation
// ---------------------------------------------------------------------------
__global__ __launch_bounds__(256) void agg_kernel(const float* __restrict__ X)
{
    int n = blockIdx.x, f = threadIdx.x;
    const float* base = X + (size_t)n * Lc * 256 + f;
    float s = 0.0f, m = -1e30f;
#pragma unroll 5
    for (int l = 0; l < Lc; l++) {
        float v = base[(size_t)l * 256];
        s += v; m = fmaxf(m, v);
    }
    g_agg[(size_t)n * 768 + f]       = s * (1.0f / Lc);
    g_agg[(size_t)n * 768 + 256 + f] = m;
    g_agg[(size_t)n * 768 + 512 + f] = (f < H) ? base[(Lc - 1) * 256] : base[0];
}

// ---------------------------------------------------------------------------
// Kernel 5: LayerNorm(512) + ReLU
// ---------------------------------------------------------------------------
__global__ __launch_bounds__(256) void ln_relu(
    const float* __restrict__ x, float* __restrict__ y,
    const float* __restrict__ gam, const float* __restrict__ bet)
{
    int row = blockIdx.x, tid = threadIdx.x;
    const float* xr = x + (size_t)row * 512;
    float v0 = xr[tid], v1 = xr[tid + 256];
    float s = v0 + v1, q = v0 * v0 + v1 * v1;
    __shared__ float ss[8], sq[8];
#pragma unroll
    for (int o = 16; o > 0; o >>= 1) {
        s += __shfl_down_sync(~0u, s, o);
        q += __shfl_down_sync(~0u, q, o);
    }
    int w = tid >> 5;
    if ((tid & 31) == 0) { ss[w] = s; sq[w] = q; }
    __syncthreads();
    if (tid == 0) {
        float S = 0.0f, Q = 0.0f;
        for (int i = 0; i < 8; i++) { S += ss[i]; Q += sq[i]; }
        ss[0] = S; sq[0] = Q;
    }
    __syncthreads();
    float mu  = ss[0] * (1.0f / 512.0f);
    float var = sq[0] * (1.0f / 512.0f) - mu * mu;
    float rs  = rsqrtf(var + 1e-5f);
    y[(size_t)row * 512 + tid]       = fmaxf((v0 - mu) * rs * gam[tid]       + bet[tid],       0.0f);
    y[(size_t)row * 512 + tid + 256] = fmaxf((v1 - mu) * rs * gam[tid + 256] + bet[tid + 256], 0.0f);
}

// ---------------------------------------------------------------------------
// Host orchestration
// ---------------------------------------------------------------------------
extern "C" void kernel_launch(void* const* d_in, const int* in_sizes, int n_in,
                              void* d_out, int out_size)
{
    const float* imu   = (const float*)d_in[0];
    const float* W_in  = (const float*)d_in[1];
    const float* b_in  = (const float*)d_in[2];
    const float* Wih[3] = {(const float*)d_in[3],  (const float*)d_in[7],  (const float*)d_in[11]};
    const float* Whh[3] = {(const float*)d_in[4],  (const float*)d_in[8],  (const float*)d_in[12]};
    const float* bih[3] = {(const float*)d_in[5],  (const float*)d_in[9],  (const float*)d_in[13]};
    const float* bhh[3] = {(const float*)d_in[6],  (const float*)d_in[10], (const float*)d_in[14]};
    const float* Wout1 = (const float*)d_in[15];
    const float* bout1 = (const float*)d_in[16];
    const float* ln_g  = (const float*)d_in[17];
    const float* ln_b  = (const float*)d_in[18];
    const float* Wout2 = (const float*)d_in[19];
    const float* bout2 = (const float*)d_in[20];
    float* out = (float*)d_out;

    float *pX0, *pXa, *pXb, *pxg, *pagg, *pt1, *pt2;
    cudaGetSymbolAddress((void**)&pX0,  g_X0);
    cudaGetSymbolAddress((void**)&pXa,  g_Xa);
    cudaGetSymbolAddress((void**)&pXb,  g_Xb);
    cudaGetSymbolAddress((void**)&pxg,  g_xg);
    cudaGetSymbolAddress((void**)&pagg, g_agg);
    cudaGetSymbolAddress((void**)&pt1,  g_t1);
    cudaGetSymbolAddress((void**)&pt2,  g_t2);

    // Whh slice 128KB + double-buffered h pairs 40KB
    constexpr int LSTM_SMEM = 128 * 64 * 16 + 2 * 4 * 5 * 128 * 8;  // 172032
    cudaFuncSetAttribute(lstm_layer,
                         cudaFuncAttributeMaxDynamicSharedMemorySize, LSTM_SMEM);

    inproj_kernel<<<(NR * 64) / 256, 256>>>(imu, W_in, b_in);

    float* Xin  = pX0;
    int    Kin  = 64;
    float* Xout = pXa;
    for (int layer = 0; layer < 3; layer++) {
        sgemm_bias<<<dim3(G4 / 128, NR / 128, 2), 256>>>(
            Xin, Wih[layer], pxg, bih[layer], bhh[layer],
            NR, G4, Kin,
            (long long)Kin * G4, (long long)NR * G4, (long long)G4);
        lstm_layer<<<128, 256, LSTM_SMEM>>>(Whh[layer], pxg, Xout);
        Xin = Xout;
        Kin = 256;
        Xout = (Xin == pXa) ? pXb : pXa;
    }
    float* Xfinal = Xin;

    agg_kernel<<<NSEQ, 256>>>(Xfinal);
    sgemm_bias<<<dim3(512 / 128, NSEQ / 128, 1), 256>>>(
        pagg, Wout1, pt1, bout1, nullptr, NSEQ, 512, 768, 0, 0, 0);
    ln_relu<<<NSEQ, 256>>>(pt1, pt2, ln_g, ln_b);
    sgemm_bias<<<dim3(256 / 128, NSEQ / 128, 1), 256>>>(
        pt2, Wout2, out, bout2, nullptr, NSEQ, 256, 512, 0, 0, 0);
}

// round 5
// speedup vs baseline: 1.4974x; 1.4974x over previous
#include <cuda_runtime.h>
#include <math.h>
#include <stdint.h>

// Problem constants
constexpr int Lc    = 50;
constexpr int NSEQ  = 32 * 40;     // 1280 sequences
constexpr int NR    = NSEQ * Lc;   // 64000 (seq,time) rows
constexpr int H     = 128;
constexpr int G4    = 512;         // 4*H gates

// ---------------------------------------------------------------------------
// Device scratch
// ---------------------------------------------------------------------------
__device__ float g_X0[(size_t)NR * 64];
__device__ float g_Xa[(size_t)NR * 256];
__device__ float g_Xb[(size_t)NR * 256];
__device__ float g_xg[2][(size_t)NR * G4];
__device__ float g_hbuf[2][2][NSEQ * H];     // [step parity][dir][row*H+col]
__device__ int   g_flags[2][2][32];          // [dir][jtile][rowgroup]
__device__ float g_agg[(size_t)NSEQ * 768];
__device__ float g_t1[(size_t)NSEQ * 512];
__device__ float g_t2[(size_t)NSEQ * 512];

// ---------------------------------------------------------------------------
// f32x2 helpers
// ---------------------------------------------------------------------------
__device__ __forceinline__ float2 ffma2(float2 a, float2 b, float2 c) {
    unsigned long long ud;
    asm("fma.rn.f32x2 %0, %1, %2, %3;"
        : "=l"(ud)
        : "l"(*(unsigned long long*)&a),
          "l"(*(unsigned long long*)&b),
          "l"(*(unsigned long long*)&c));
    float2 d; *(unsigned long long*)&d = ud; return d;
}
__device__ __forceinline__ float2 pack2(float lo, float hi) {
    float2 r; r.x = lo; r.y = hi; return r;
}
__device__ __forceinline__ float sigm_(float x) {
    return __fdividef(1.0f, 1.0f + __expf(-x));
}
__device__ __forceinline__ float tanh_(float x) {
    return __fdividef(2.0f, 1.0f + __expf(-2.0f * x)) - 1.0f;
}

// ---------------------------------------------------------------------------
// reset pairwise-sync flags (once per replay)
// ---------------------------------------------------------------------------
__global__ void reset_flags() {
    ((int*)g_flags)[threadIdx.x] = 0;
}

// ---------------------------------------------------------------------------
// Kernel 1: input projection
// ---------------------------------------------------------------------------
__global__ __launch_bounds__(256) void inproj_kernel(
    const float* __restrict__ imu, const float* __restrict__ Win,
    const float* __restrict__ bin)
{
    int idx = blockIdx.x * 256 + threadIdx.x;
    int row = idx >> 6;
    int jj  = idx & 63;
    int l   = row % Lc;
    const float* xr = imu + (size_t)row * 6;
    float t    = (float)l * (1.0f / 49.0f);
    float rate = 1.0f;
    float acc = bin[jj];
#pragma unroll
    for (int k = 0; k < 6; k++) acc = fmaf(xr[k], Win[k * 64 + jj], acc);
    acc = fmaf(t,    Win[6 * 64 + jj], acc);
    acc = fmaf(rate, Win[7 * 64 + jj], acc);
    g_X0[(size_t)row * 64 + jj] = fmaxf(acc, 0.0f);
}

// ---------------------------------------------------------------------------
// Kernel 2: SGEMM + bias, f32x2, double-buffered smem
// ---------------------------------------------------------------------------
__global__ __launch_bounds__(256) void sgemm_bias(
    const float* __restrict__ A, const float* __restrict__ B,
    float* __restrict__ C,
    const float* __restrict__ bias1, const float* __restrict__ bias2,
    int M, int N, int K,
    long long sB, long long sC, long long sBias)
{
    constexpr int BM = 128, BN = 128, BK = 8, TM = 8, TN = 8;
    __shared__ float As[2][BK][BM];
    __shared__ float Bs[2][BK][BN];

    const int dir = blockIdx.z;
    B += (size_t)dir * sB;
    C += (size_t)dir * sC;
    const float* b1 = bias1 + (size_t)dir * sBias;
    const float* b2 = bias2 ? bias2 + (size_t)dir * sBias : nullptr;
    const bool hasB2 = (b2 != nullptr);

    const int cRow = blockIdx.y, cCol = blockIdx.x;
    const int tid  = threadIdx.x;
    const int tCol = tid % (BN / TN);
    const int tRow = tid / (BN / TN);

    const int aRow = tid >> 1;
    const int aCol = (tid & 1) * 4;
    const int bRow = tid >> 5;
    const int bCol = (tid & 31) * 4;

    const float* Ab = A + (size_t)cRow * BM * K;
    const float* Bb = B + cCol * BN;

    float2 acc2[TM][TN / 2];
#pragma unroll
    for (int i = 0; i < TM; i++)
#pragma unroll
        for (int j = 0; j < TN / 2; j++) acc2[i][j] = pack2(0.f, 0.f);

    float regM[TM];
    const int niter = K / BK;

    {
        float4 av = *(const float4*)(Ab + (size_t)aRow * K + aCol);
        As[0][aCol + 0][aRow] = av.x;
        As[0][aCol + 1][aRow] = av.y;
        As[0][aCol + 2][aRow] = av.z;
        As[0][aCol + 3][aRow] = av.w;
        *(float4*)&Bs[0][bRow][bCol] =
            *(const float4*)(Bb + (size_t)bRow * N + bCol);
    }
    __syncthreads();

    for (int it = 0; it < niter; it++) {
        const int cur = it & 1, nxt = cur ^ 1;
        float4 av, bv;
        const bool more = (it + 1 < niter);
        if (more) {
            int k0 = (it + 1) * BK;
            av = *(const float4*)(Ab + (size_t)aRow * K + k0 + aCol);
            bv = *(const float4*)(Bb + (size_t)(k0 + bRow) * N + bCol);
        }
#pragma unroll
        for (int k = 0; k < BK; k++) {
            *(float4*)&regM[0] = *(const float4*)&As[cur][k][tRow * TM];
            *(float4*)&regM[4] = *(const float4*)&As[cur][k][tRow * TM + 4];
            float4 bn0 = *(const float4*)&Bs[cur][k][tCol * TN];
            float4 bn1 = *(const float4*)&Bs[cur][k][tCol * TN + 4];
            float2 n0 = pack2(bn0.x, bn0.y), n1 = pack2(bn0.z, bn0.w);
            float2 n2 = pack2(bn1.x, bn1.y), n3 = pack2(bn1.z, bn1.w);
#pragma unroll
            for (int i = 0; i < TM; i++) {
                float2 m2 = pack2(regM[i], regM[i]);
                acc2[i][0] = ffma2(m2, n0, acc2[i][0]);
                acc2[i][1] = ffma2(m2, n1, acc2[i][1]);
                acc2[i][2] = ffma2(m2, n2, acc2[i][2]);
                acc2[i][3] = ffma2(m2, n3, acc2[i][3]);
            }
        }
        if (more) {
            As[nxt][aCol + 0][aRow] = av.x;
            As[nxt][aCol + 1][aRow] = av.y;
            As[nxt][aCol + 2][aRow] = av.z;
            As[nxt][aCol + 3][aRow] = av.w;
            *(float4*)&Bs[nxt][bRow][bCol] = bv;
        }
        __syncthreads();
    }

#pragma unroll
    for (int i = 0; i < TM; i++) {
        size_t row = (size_t)cRow * BM + tRow * TM + i;
        float* Cr = C + row * N + cCol * BN + tCol * TN;
        const int colb = cCol * BN + tCol * TN;
#pragma unroll
        for (int j2 = 0; j2 < TN / 2; j2++) {
            float vx = acc2[i][j2].x + b1[colb + 2 * j2];
            float vy = acc2[i][j2].y + b1[colb + 2 * j2 + 1];
            if (hasB2) { vx += b2[colb + 2 * j2]; vy += b2[colb + 2 * j2 + 1]; }
            Cr[2 * j2]     = vx;
            Cr[2 * j2 + 1] = vy;
        }
    }
}

// ---------------------------------------------------------------------------
// Kernel 3: PERSISTENT BiLSTM layer. 128 CTAs x 512 threads.
// CTA = (dir, jt, rowgroup-of-40). Thread = (jj in 0..63, rg in 0..7, 5 rows).
// Own h half -> local smem directly; partner half via global + release flag.
// hs pair layout per buffer: [rg8][p3][k128] float2, p=2 holds (row4, junk).
// ---------------------------------------------------------------------------
__global__ __launch_bounds__(512) void lstm_layer(
    const float* __restrict__ Whh,
    const float* __restrict__ xgb,
    float* __restrict__ Xout,
    int layer)
{
    extern __shared__ float smem[];
    float4* ws  = (float4*)smem;                        // [128][64] gate quads
    float*  hsf = smem + 128 * 64 * 4;                  // 2 bufs x 8*3*128 float2
    constexpr int HBUF = 8 * 3 * 128 * 2;               // floats per buffer

    const int bx   = blockIdx.x;
    const int dir  = bx >> 6;
    const int jt   = (bx >> 5) & 1;
    const int rgI  = bx & 31;
    const int row0 = rgI * 40;
    const int tid  = threadIdx.x;
    const int jj   = tid & 63;
    const int rg   = tid >> 6;             // 0..7, rows rg*5..rg*5+4
    const int col  = jt * 64 + jj;
    const int base = layer * Lc;

    const float* W   = Whh + (size_t)dir * (H * G4);
    const float* xgd = xgb + (size_t)dir * NR * G4;
    int* myflag = &g_flags[dir][jt][rgI];
    int* pflag  = &g_flags[dir][jt ^ 1][rgI];

    // Stage Whh slice: ws[k*64+j] = {W[k][jt*64+j + g*128]}
    for (int idx = tid; idx < 128 * 64; idx += 512) {
        int k = idx >> 6, j = idx & 63;
        const float* wk = W + (size_t)k * G4 + jt * 64 + j;
        ws[idx] = make_float4(wk[0], wk[128], wk[256], wk[384]);
    }
    __syncthreads();

    float c[5];
#pragma unroll
    for (int r = 0; r < 5; r++) c[r] = 0.0f;

    for (int step = 0; step < Lc; step++) {
        const int tin = dir ? (Lc - 1 - step) : step;

        // xg prefetch (issues LDGs before the flag wait)
        float2 acc2[4][2];
        float  accs[4];
#pragma unroll
        for (int p = 0; p < 2; p++) {
            int rowA = row0 + rg * 5 + 2 * p;
            const float* xa = xgd + ((size_t)rowA * Lc + tin) * G4 + col;
            const float* xb = xa + (size_t)Lc * G4;
#pragma unroll
            for (int g = 0; g < 4; g++)
                acc2[g][p] = pack2(xa[g * 128], xb[g * 128]);
        }
        {
            int rowA = row0 + rg * 5 + 4;
            const float* xa = xgd + ((size_t)rowA * Lc + tin) * G4 + col;
#pragma unroll
            for (int g = 0; g < 4; g++) accs[g] = xa[g * 128];
        }

        if (step > 0) {
            // wait for partner's h(step-1)
            if (tid == 0) {
                const int want = base + step;
                int v;
                do {
                    asm volatile("ld.acquire.gpu.global.b32 %0, [%1];"
                                 : "=r"(v) : "l"(pflag) : "memory");
                } while (v < want);
            }
            __syncthreads();

            // restage partner half into pair layout of buffer (step-1)&1
            float* hc_buf = hsf + ((step + 1) & 1) * HBUF;
            const float* hbg = g_hbuf[(step + 1) & 1][dir];
            const int pcol0 = (jt ^ 1) * 64;
#pragma unroll
            for (int i = 0; i < 5; i++) {
                int idx = tid + i * 512;               // 0..2559
                int rl = idx >> 6, j = idx & 63;
                int kk = pcol0 + j;
                float v = hbg[(size_t)(row0 + rl) * H + kk];
                int trg = rl / 5, wr = rl % 5;
                hc_buf[((trg * 3 + (wr >> 1)) * 128 + kk) * 2 + (wr & 1)] = v;
            }
            __syncthreads();

            // k-loop: software-pipelined
            const float* hrow = hsf + ((step + 1) & 1) * HBUF + rg * 3 * 128 * 2;
            const float2* hrow2 = (const float2*)hrow;
            float4 w4 = ws[jj];
            float2 ha = hrow2[0];
            float2 hb = hrow2[128];
            float  hc = hrow[2 * 128 * 2];
#pragma unroll 4
            for (int k = 0; k < 128; k++) {
                float4 w4n; float2 han, hbn; float hcn;
                if (k < 127) {
                    w4n = ws[(k + 1) * 64 + jj];
                    han = hrow2[k + 1];
                    hbn = hrow2[128 + k + 1];
                    hcn = hrow[(2 * 128 + k + 1) * 2];
                }
                float2 w0 = pack2(w4.x, w4.x);
                float2 w1 = pack2(w4.y, w4.y);
                float2 w2 = pack2(w4.z, w4.z);
                float2 w3 = pack2(w4.w, w4.w);
                acc2[0][0] = ffma2(ha, w0, acc2[0][0]);
                acc2[1][0] = ffma2(ha, w1, acc2[1][0]);
                acc2[2][0] = ffma2(ha, w2, acc2[2][0]);
                acc2[3][0] = ffma2(ha, w3, acc2[3][0]);
                acc2[0][1] = ffma2(hb, w0, acc2[0][1]);
                acc2[1][1] = ffma2(hb, w1, acc2[1][1]);
                acc2[2][1] = ffma2(hb, w2, acc2[2][1]);
                acc2[3][1] = ffma2(hb, w3, acc2[3][1]);
                accs[0] = fmaf(hc, w4.x, accs[0]);
                accs[1] = fmaf(hc, w4.y, accs[1]);
                accs[2] = fmaf(hc, w4.z, accs[2]);
                accs[3] = fmaf(hc, w4.w, accs[3]);
                w4 = w4n; ha = han; hb = hbn; hc = hcn;
            }
        }

        // gates + state update
        float hval[5];
#pragma unroll
        for (int p = 0; p < 2; p++) {
            float i0 = sigm_(acc2[0][p].x), i1 = sigm_(acc2[0][p].y);
            float f0 = sigm_(acc2[1][p].x), f1 = sigm_(acc2[1][p].y);
            float ga = tanh_(acc2[2][p].x), gb = tanh_(acc2[2][p].y);
            float o0 = sigm_(acc2[3][p].x), o1 = sigm_(acc2[3][p].y);
            float c0 = fmaf(f0, c[2 * p],     i0 * ga);
            float c1 = fmaf(f1, c[2 * p + 1], i1 * gb);
            c[2 * p] = c0; c[2 * p + 1] = c1;
            hval[2 * p]     = o0 * tanh_(c0);
            hval[2 * p + 1] = o1 * tanh_(c1);
        }
        {
            float ig = sigm_(accs[0]);
            float fg = sigm_(accs[1]);
            float gg = tanh_(accs[2]);
            float og = sigm_(accs[3]);
            float cn = fmaf(fg, c[4], ig * gg);
            c[4] = cn;
            hval[4] = og * tanh_(cn);
        }

        // publish: local smem (own half) + global (for partner) + flag — FIRST
        if (step < Lc - 1) {
            float* hw_buf = hsf + (step & 1) * HBUF;
            float* hbg = g_hbuf[step & 1][dir];
#pragma unroll
            for (int r = 0; r < 5; r++) {
                hw_buf[((rg * 3 + (r >> 1)) * 128 + col) * 2 + (r & 1)] = hval[r];
                hbg[(size_t)(row0 + rg * 5 + r) * H + col] = hval[r];
            }
            __syncthreads();
            if (tid == 0) {
                int dummy;
                asm volatile("atom.release.gpu.global.exch.b32 %0, [%1], %2;"
                             : "=r"(dummy) : "l"(myflag), "r"(base + step + 1)
                             : "memory");
            }
        }

        // layer output (fire-and-forget, after the flag)
#pragma unroll
        for (int r = 0; r < 5; r++) {
            int row = row0 + rg * 5 + r;
            Xout[((size_t)row * Lc + tin) * 256 + dir * H + col] = hval[r];
        }
    }
}

// ---------------------------------------------------------------------------
// Kernel 4: aggregation
// ---------------------------------------------------------------------------
__global__ __launch_bounds__(256) void agg_kernel(const float* __restrict__ X)
{
    int n = blockIdx.x, f = threadIdx.x;
    const float* base = X + (size_t)n * Lc * 256 + f;
    float s = 0.0f, m = -1e30f;
#pragma unroll 5
    for (int l = 0; l < Lc; l++) {
        float v = base[(size_t)l * 256];
        s += v; m = fmaxf(m, v);
    }
    g_agg[(size_t)n * 768 + f]       = s * (1.0f / Lc);
    g_agg[(size_t)n * 768 + 256 + f] = m;
    g_agg[(size_t)n * 768 + 512 + f] = (f < H) ? base[(Lc - 1) * 256] : base[0];
}

// ---------------------------------------------------------------------------
// Kernel 5: LayerNorm(512) + ReLU
// ---------------------------------------------------------------------------
__global__ __launch_bounds__(256) void ln_relu(
    const float* __restrict__ x, float* __restrict__ y,
    const float* __restrict__ gam, const float* __restrict__ bet)
{
    int row = blockIdx.x, tid = threadIdx.x;
    const float* xr = x + (size_t)row * 512;
    float v0 = xr[tid], v1 = xr[tid + 256];
    float s = v0 + v1, q = v0 * v0 + v1 * v1;
    __shared__ float ss[8], sq[8];
#pragma unroll
    for (int o = 16; o > 0; o >>= 1) {
        s += __shfl_down_sync(~0u, s, o);
        q += __shfl_down_sync(~0u, q, o);
    }
    int w = tid >> 5;
    if ((tid & 31) == 0) { ss[w] = s; sq[w] = q; }
    __syncthreads();
    if (tid == 0) {
        float S = 0.0f, Q = 0.0f;
        for (int i = 0; i < 8; i++) { S += ss[i]; Q += sq[i]; }
        ss[0] = S; sq[0] = Q;
    }
    __syncthreads();
    float mu  = ss[0] * (1.0f / 512.0f);
    float var = sq[0] * (1.0f / 512.0f) - mu * mu;
    float rs  = rsqrtf(var + 1e-5f);
    y[(size_t)row * 512 + tid]       = fmaxf((v0 - mu) * rs * gam[tid]       + bet[tid],       0.0f);
    y[(size_t)row * 512 + tid + 256] = fmaxf((v1 - mu) * rs * gam[tid + 256] + bet[tid + 256], 0.0f);
}

// ---------------------------------------------------------------------------
// Host orchestration
// ---------------------------------------------------------------------------
extern "C" void kernel_launch(void* const* d_in, const int* in_sizes, int n_in,
                              void* d_out, int out_size)
{
    const float* imu   = (const float*)d_in[0];
    const float* W_in  = (const float*)d_in[1];
    const float* b_in  = (const float*)d_in[2];
    const float* Wih[3] = {(const float*)d_in[3],  (const float*)d_in[7],  (const float*)d_in[11]};
    const float* Whh[3] = {(const float*)d_in[4],  (const float*)d_in[8],  (const float*)d_in[12]};
    const float* bih[3] = {(const float*)d_in[5],  (const float*)d_in[9],  (const float*)d_in[13]};
    const float* bhh[3] = {(const float*)d_in[6],  (const float*)d_in[10], (const float*)d_in[14]};
    const float* Wout1 = (const float*)d_in[15];
    const float* bout1 = (const float*)d_in[16];
    const float* ln_g  = (const float*)d_in[17];
    const float* ln_b  = (const float*)d_in[18];
    const float* Wout2 = (const float*)d_in[19];
    const float* bout2 = (const float*)d_in[20];
    float* out = (float*)d_out;

    float *pX0, *pXa, *pXb, *pxg, *pagg, *pt1, *pt2;
    cudaGetSymbolAddress((void**)&pX0,  g_X0);
    cudaGetSymbolAddress((void**)&pXa,  g_Xa);
    cudaGetSymbolAddress((void**)&pXb,  g_Xb);
    cudaGetSymbolAddress((void**)&pxg,  g_xg);
    cudaGetSymbolAddress((void**)&pagg, g_agg);
    cudaGetSymbolAddress((void**)&pt1,  g_t1);
    cudaGetSymbolAddress((void**)&pt2,  g_t2);

    // Whh slice 128KB + double-buffered pair h bufs 2*24KB
    constexpr int LSTM_SMEM = 128 * 64 * 16 + 2 * 8 * 3 * 128 * 8;  // 180224
    cudaFuncSetAttribute(lstm_layer,
                         cudaFuncAttributeMaxDynamicSharedMemorySize, LSTM_SMEM);

    reset_flags<<<1, 128>>>();
    inproj_kernel<<<(NR * 64) / 256, 256>>>(imu, W_in, b_in);

    float* Xin  = pX0;
    int    Kin  = 64;
    float* Xout = pXa;
    for (int layer = 0; layer < 3; layer++) {
        sgemm_bias<<<dim3(G4 / 128, NR / 128, 2), 256>>>(
            Xin, Wih[layer], pxg, bih[layer], bhh[layer],
            NR, G4, Kin,
            (long long)Kin * G4, (long long)NR * G4, (long long)G4);
        lstm_layer<<<128, 512, LSTM_SMEM>>>(Whh[layer], pxg, Xout, layer);
        Xin = Xout;
        Kin = 256;
        Xout = (Xin == pXa) ? pXb : pXa;
    }
    float* Xfinal = Xin;

    agg_kernel<<<NSEQ, 256>>>(Xfinal);
    sgemm_bias<<<dim3(512 / 128, NSEQ / 128, 1), 256>>>(
        pagg, Wout1, pt1, bout1, nullptr, NSEQ, 512, 768, 0, 0, 0);
    ln_relu<<<NSEQ, 256>>>(pt1, pt2, ln_g, ln_b);
    sgemm_bias<<<dim3(256 / 128, NSEQ / 128, 1), 256>>>(
        pt2, Wout2, out, bout2, nullptr, NSEQ, 256, 512, 0, 0, 0);
}

// round 6
// speedup vs baseline: 2.1387x; 1.4283x over previous
#include <cuda_runtime.h>
#include <math.h>
#include <stdint.h>

// Problem constants
constexpr int Lc    = 50;
constexpr int NSEQ  = 32 * 40;     // 1280 sequences
constexpr int NR    = NSEQ * Lc;   // 64000 (seq,time) rows
constexpr int H     = 128;
constexpr int G4    = 512;         // 4*H gates

// ---------------------------------------------------------------------------
// Device scratch
// ---------------------------------------------------------------------------
__device__ float g_X0[(size_t)NR * 64];
__device__ float g_Xa[(size_t)NR * 256];
__device__ float g_Xb[(size_t)NR * 256];
__device__ float g_xg[2][(size_t)NR * G4];
__device__ float g_hbuf[2][2][NSEQ * H];     // [step parity][dir][row*H+col]
__device__ int   g_flags[2][2][32];          // [dir][jtile][rowgroup]
__device__ float g_agg[(size_t)NSEQ * 768];
__device__ float g_t1[(size_t)NSEQ * 512];
__device__ float g_t2[(size_t)NSEQ * 512];

// ---------------------------------------------------------------------------
// helpers
// ---------------------------------------------------------------------------
__device__ __forceinline__ float2 ffma2(float2 a, float2 b, float2 c) {
    unsigned long long ud;
    asm("fma.rn.f32x2 %0, %1, %2, %3;"
        : "=l"(ud)
        : "l"(*(unsigned long long*)&a),
          "l"(*(unsigned long long*)&b),
          "l"(*(unsigned long long*)&c));
    float2 d; *(unsigned long long*)&d = ud; return d;
}
__device__ __forceinline__ float2 pack2(float lo, float hi) {
    float2 r; r.x = lo; r.y = hi; return r;
}
__device__ __forceinline__ float sigm_(float x) {
    return __fdividef(1.0f, 1.0f + __expf(-x));
}
__device__ __forceinline__ float tanh_(float x) {
    return __fdividef(2.0f, 1.0f + __expf(-2.0f * x)) - 1.0f;
}
__device__ __forceinline__ uint32_t f2tf(float x) {
    uint32_t r;
    asm("cvt.rna.tf32.f32 %0, %1;" : "=r"(r) : "f"(x));
    return r;
}
__device__ __forceinline__ void mma_tf32(float* d, const uint32_t* a,
                                         const uint32_t* b) {
    asm volatile(
        "mma.sync.aligned.m16n8k8.row.col.f32.tf32.tf32.f32 "
        "{%0,%1,%2,%3}, {%4,%5,%6,%7}, {%8,%9}, {%0,%1,%2,%3};\n"
        : "+f"(d[0]), "+f"(d[1]), "+f"(d[2]), "+f"(d[3])
        : "r"(a[0]), "r"(a[1]), "r"(a[2]), "r"(a[3]), "r"(b[0]), "r"(b[1]));
}

// ---------------------------------------------------------------------------
// reset pairwise-sync flags (once per replay)
// ---------------------------------------------------------------------------
__global__ void reset_flags() {
    ((int*)g_flags)[threadIdx.x] = 0;
}

// ---------------------------------------------------------------------------
// Kernel 1: input projection
// ---------------------------------------------------------------------------
__global__ __launch_bounds__(256) void inproj_kernel(
    const float* __restrict__ imu, const float* __restrict__ Win,
    const float* __restrict__ bin)
{
    int idx = blockIdx.x * 256 + threadIdx.x;
    int row = idx >> 6;
    int jj  = idx & 63;
    int l   = row % Lc;
    const float* xr = imu + (size_t)row * 6;
    float t    = (float)l * (1.0f / 49.0f);
    float rate = 1.0f;
    float acc = bin[jj];
#pragma unroll
    for (int k = 0; k < 6; k++) acc = fmaf(xr[k], Win[k * 64 + jj], acc);
    acc = fmaf(t,    Win[6 * 64 + jj], acc);
    acc = fmaf(rate, Win[7 * 64 + jj], acc);
    g_X0[(size_t)row * 64 + jj] = fmaxf(acc, 0.0f);
}

// ---------------------------------------------------------------------------
// Kernel 2: tf32 tensor-core GEMM + bias.
// C[M,N] = A[M,K] @ B[K,N] + b1 (+ b2). dir = blockIdx.x / nbx offsets B,C,b.
// 128x128x32 tiles, 8 warps x (64x32), m16n8k8 tf32 HMMA, double-buffered.
// smem layouts arranged so every fragment load is a single LDS.64.
// ---------------------------------------------------------------------------
constexpr int APITCH = 132;   // words per (ks,c) A row
constexpr int BPITCH = 260;   // words per (ks,kp) B row
constexpr int ASZ = 4 * 8 * APITCH;   // words per A buffer
constexpr int BSZ = 4 * 4 * BPITCH;   // words per B buffer
constexpr int GEMM_SMEM = (2 * ASZ + 2 * BSZ) * 4;  // bytes

__device__ __forceinline__ int asI(int buf, int ks, int c, int q) {
    return ((buf * 4 + ks) * 8 + c) * APITCH + q;
}
__device__ __forceinline__ int bsI(int buf, int ks, int kp, int q) {
    return ((buf * 4 + ks) * 4 + kp) * BPITCH + q;
}

__global__ __launch_bounds__(256) void tf32_gemm(
    const float* __restrict__ A, const float* __restrict__ B,
    float* __restrict__ C,
    const float* __restrict__ bias1, const float* __restrict__ bias2,
    int M, int N, int K,
    long long sB, long long sC, long long sBias, int nbx)
{
    extern __shared__ uint32_t sm[];
    uint32_t* As = sm;              // [2][4][8][APITCH]
    uint32_t* Bs = sm + 2 * ASZ;    // [2][4][4][BPITCH]

    const int dir = blockIdx.x / nbx;
    const int nb  = blockIdx.x % nbx;
    const int mb  = blockIdx.y;
    B += (size_t)dir * sB;
    C += (size_t)dir * sC;
    const float* b1 = bias1 + (size_t)dir * sBias;
    const float* b2 = bias2 ? bias2 + (size_t)dir * sBias : nullptr;
    const bool hasB2 = (b2 != nullptr);

    const int tid  = threadIdx.x;
    const int warp = tid >> 5, lane = tid & 31;
    const int wR = warp >> 2, wC = warp & 3;     // warp tile (64 rows, 32 cols)
    const int g  = lane >> 2, tig = lane & 3;

    const float* Ab = A + (size_t)(mb * 128) * K;
    const float* Bb = B + nb * 128;

    const int lr  = tid >> 3;         // 0..31
    const int lc4 = (tid & 7) * 4;    // 0,4,..,28
    const int aks = lc4 >> 3, ac0 = lc4 & 7;
    const int bks = lr >> 3, br8 = lr & 7;
    const int bkp = br8 & 3, bhalf = br8 >> 2;

    float acc[4][4][4];
#pragma unroll
    for (int mt = 0; mt < 4; mt++)
#pragma unroll
        for (int nt = 0; nt < 4; nt++)
#pragma unroll
            for (int q = 0; q < 4; q++) acc[mt][nt][q] = 0.0f;

    const int niter = K / 32;

    // prologue: k-tile 0 -> buffer 0
    {
#pragma unroll
        for (int i = 0; i < 4; i++) {
            int r = lr + i * 32;
            float4 v = *(const float4*)(Ab + (size_t)r * K + lc4);
            int q = ((r >> 4) << 4) + ((r & 7) << 1) + ((r >> 3) & 1);
            uint32_t* d = &As[asI(0, aks, ac0, q)];
            d[0] = f2tf(v.x); d[APITCH] = f2tf(v.y);
            d[2 * APITCH] = f2tf(v.z); d[3 * APITCH] = f2tf(v.w);
        }
#pragma unroll
        for (int i = 0; i < 4; i++) {
            int col = lc4 + i * 32;
            float4 v = *(const float4*)(Bb + (size_t)lr * N + col);
            uint32_t* d = &Bs[bsI(0, bks, bkp, col * 2 + bhalf)];
            d[0] = f2tf(v.x); d[2] = f2tf(v.y);
            d[4] = f2tf(v.z); d[6] = f2tf(v.w);
        }
    }
    __syncthreads();

    for (int it = 0; it < niter; it++) {
        const int cur = it & 1, nxt = cur ^ 1;
        const bool more = (it + 1 < niter);
        float4 av[4], bv[4];
        if (more) {
            int k0 = (it + 1) * 32;
#pragma unroll
            for (int i = 0; i < 4; i++) {
                av[i] = *(const float4*)(Ab + (size_t)(lr + i * 32) * K + k0 + lc4);
                bv[i] = *(const float4*)(Bb + (size_t)(k0 + lr) * N + lc4 + i * 32);
            }
        }

#pragma unroll
        for (int ks = 0; ks < 4; ks++) {
            uint32_t af[4][4];
#pragma unroll
            for (int mt = 0; mt < 4; mt++) {
                int q = ((wR * 4 + mt) << 4) + (g << 1);
                uint2 u0 = *(const uint2*)&As[asI(cur, ks, tig, q)];
                uint2 u1 = *(const uint2*)&As[asI(cur, ks, tig + 4, q)];
                af[mt][0] = u0.x; af[mt][1] = u0.y;
                af[mt][2] = u1.x; af[mt][3] = u1.y;
            }
            uint32_t bf[4][2];
#pragma unroll
            for (int nt = 0; nt < 4; nt++) {
                int n = wC * 32 + nt * 8 + g;
                uint2 u = *(const uint2*)&Bs[bsI(cur, ks, tig, n * 2)];
                bf[nt][0] = u.x; bf[nt][1] = u.y;
            }
#pragma unroll
            for (int mt = 0; mt < 4; mt++)
#pragma unroll
                for (int nt = 0; nt < 4; nt++)
                    mma_tf32(acc[mt][nt], af[mt], bf[nt]);
        }

        if (more) {
#pragma unroll
            for (int i = 0; i < 4; i++) {
                int r = lr + i * 32;
                int q = ((r >> 4) << 4) + ((r & 7) << 1) + ((r >> 3) & 1);
                uint32_t* d = &As[asI(nxt, aks, ac0, q)];
                d[0] = f2tf(av[i].x); d[APITCH] = f2tf(av[i].y);
                d[2 * APITCH] = f2tf(av[i].z); d[3 * APITCH] = f2tf(av[i].w);
                int col = lc4 + i * 32;
                uint32_t* db = &Bs[bsI(nxt, bks, bkp, col * 2 + bhalf)];
                db[0] = f2tf(bv[i].x); db[2] = f2tf(bv[i].y);
                db[4] = f2tf(bv[i].z); db[6] = f2tf(bv[i].w);
            }
        }
        __syncthreads();
    }

    // epilogue
#pragma unroll
    for (int mt = 0; mt < 4; mt++) {
        int row = mb * 128 + wR * 64 + mt * 16 + g;
#pragma unroll
        for (int nt = 0; nt < 4; nt++) {
            int colg = nb * 128 + wC * 32 + nt * 8 + 2 * tig;
            float bx = b1[colg], by = b1[colg + 1];
            if (hasB2) { bx += b2[colg]; by += b2[colg + 1]; }
            float2 v0 = pack2(acc[mt][nt][0] + bx, acc[mt][nt][1] + by);
            float2 v1 = pack2(acc[mt][nt][2] + bx, acc[mt][nt][3] + by);
            *(float2*)(C + (size_t)row * N + colg)       = v0;
            *(float2*)(C + (size_t)(row + 8) * N + colg) = v1;
        }
    }
}

// ---------------------------------------------------------------------------
// Kernel 3: PERSISTENT BiLSTM layer (round-5 winner, unchanged)
// ---------------------------------------------------------------------------
__global__ __launch_bounds__(512) void lstm_layer(
    const float* __restrict__ Whh,
    const float* __restrict__ xgb,
    float* __restrict__ Xout,
    int layer)
{
    extern __shared__ float smem[];
    float4* ws  = (float4*)smem;                        // [128][64] gate quads
    float*  hsf = smem + 128 * 64 * 4;
    constexpr int HBUF = 8 * 3 * 128 * 2;

    const int bx   = blockIdx.x;
    const int dir  = bx >> 6;
    const int jt   = (bx >> 5) & 1;
    const int rgI  = bx & 31;
    const int row0 = rgI * 40;
    const int tid  = threadIdx.x;
    const int jj   = tid & 63;
    const int rg   = tid >> 6;
    const int col  = jt * 64 + jj;
    const int base = layer * Lc;

    const float* W   = Whh + (size_t)dir * (H * G4);
    const float* xgd = xgb + (size_t)dir * NR * G4;
    int* myflag = &g_flags[dir][jt][rgI];
    int* pflag  = &g_flags[dir][jt ^ 1][rgI];

    for (int idx = tid; idx < 128 * 64; idx += 512) {
        int k = idx >> 6, j = idx & 63;
        const float* wk = W + (size_t)k * G4 + jt * 64 + j;
        ws[idx] = make_float4(wk[0], wk[128], wk[256], wk[384]);
    }
    __syncthreads();

    float c[5];
#pragma unroll
    for (int r = 0; r < 5; r++) c[r] = 0.0f;

    for (int step = 0; step < Lc; step++) {
        const int tin = dir ? (Lc - 1 - step) : step;

        float2 acc2[4][2];
        float  accs[4];
#pragma unroll
        for (int p = 0; p < 2; p++) {
            int rowA = row0 + rg * 5 + 2 * p;
            const float* xa = xgd + ((size_t)rowA * Lc + tin) * G4 + col;
            const float* xb = xa + (size_t)Lc * G4;
#pragma unroll
            for (int gi = 0; gi < 4; gi++)
                acc2[gi][p] = pack2(xa[gi * 128], xb[gi * 128]);
        }
        {
            int rowA = row0 + rg * 5 + 4;
            const float* xa = xgd + ((size_t)rowA * Lc + tin) * G4 + col;
#pragma unroll
            for (int gi = 0; gi < 4; gi++) accs[gi] = xa[gi * 128];
        }

        if (step > 0) {
            if (tid == 0) {
                const int want = base + step;
                int v;
                do {
                    asm volatile("ld.acquire.gpu.global.b32 %0, [%1];"
                                 : "=r"(v) : "l"(pflag) : "memory");
                } while (v < want);
            }
            __syncthreads();

            float* hc_buf = hsf + ((step + 1) & 1) * HBUF;
            const float* hbg = g_hbuf[(step + 1) & 1][dir];
            const int pcol0 = (jt ^ 1) * 64;
#pragma unroll
            for (int i = 0; i < 5; i++) {
                int idx = tid + i * 512;
                int rl = idx >> 6, j = idx & 63;
                int kk = pcol0 + j;
                float v = hbg[(size_t)(row0 + rl) * H + kk];
                int trg = rl / 5, wr = rl % 5;
                hc_buf[((trg * 3 + (wr >> 1)) * 128 + kk) * 2 + (wr & 1)] = v;
            }
            __syncthreads();

            const float* hrow = hsf + ((step + 1) & 1) * HBUF + rg * 3 * 128 * 2;
            const float2* hrow2 = (const float2*)hrow;
            float4 w4 = ws[jj];
            float2 ha = hrow2[0];
            float2 hb = hrow2[128];
            float  hc = hrow[2 * 128 * 2];
#pragma unroll 4
            for (int k = 0; k < 128; k++) {
                float4 w4n; float2 han, hbn; float hcn;
                if (k < 127) {
                    w4n = ws[(k + 1) * 64 + jj];
                    han = hrow2[k + 1];
                    hbn = hrow2[128 + k + 1];
                    hcn = hrow[(2 * 128 + k + 1) * 2];
                }
                float2 w0 = pack2(w4.x, w4.x);
                float2 w1 = pack2(w4.y, w4.y);
                float2 w2 = pack2(w4.z, w4.z);
                float2 w3 = pack2(w4.w, w4.w);
                acc2[0][0] = ffma2(ha, w0, acc2[0][0]);
                acc2[1][0] = ffma2(ha, w1, acc2[1][0]);
                acc2[2][0] = ffma2(ha, w2, acc2[2][0]);
                acc2[3][0] = ffma2(ha, w3, acc2[3][0]);
                acc2[0][1] = ffma2(hb, w0, acc2[0][1]);
                acc2[1][1] = ffma2(hb, w1, acc2[1][1]);
                acc2[2][1] = ffma2(hb, w2, acc2[2][1]);
                acc2[3][1] = ffma2(hb, w3, acc2[3][1]);
                accs[0] = fmaf(hc, w4.x, accs[0]);
                accs[1] = fmaf(hc, w4.y, accs[1]);
                accs[2] = fmaf(hc, w4.z, accs[2]);
                accs[3] = fmaf(hc, w4.w, accs[3]);
                w4 = w4n; ha = han; hb = hbn; hc = hcn;
            }
        }

        float hval[5];
#pragma unroll
        for (int p = 0; p < 2; p++) {
            float i0 = sigm_(acc2[0][p].x), i1 = sigm_(acc2[0][p].y);
            float f0 = sigm_(acc2[1][p].x), f1 = sigm_(acc2[1][p].y);
            float ga = tanh_(acc2[2][p].x), gb = tanh_(acc2[2][p].y);
            float o0 = sigm_(acc2[3][p].x), o1 = sigm_(acc2[3][p].y);
            float c0 = fmaf(f0, c[2 * p],     i0 * ga);
            float c1 = fmaf(f1, c[2 * p + 1], i1 * gb);
            c[2 * p] = c0; c[2 * p + 1] = c1;
            hval[2 * p]     = o0 * tanh_(c0);
            hval[2 * p + 1] = o1 * tanh_(c1);
        }
        {
            float ig = sigm_(accs[0]);
            float fg = sigm_(accs[1]);
            float gg = tanh_(accs[2]);
            float og = sigm_(accs[3]);
            float cn = fmaf(fg, c[4], ig * gg);
            c[4] = cn;
            hval[4] = og * tanh_(cn);
        }

        if (step < Lc - 1) {
            float* hw_buf = hsf + (step & 1) * HBUF;
            float* hbg = g_hbuf[step & 1][dir];
#pragma unroll
            for (int r = 0; r < 5; r++) {
                hw_buf[((rg * 3 + (r >> 1)) * 128 + col) * 2 + (r & 1)] = hval[r];
                hbg[(size_t)(row0 + rg * 5 + r) * H + col] = hval[r];
            }
            __syncthreads();
            if (tid == 0) {
                int dummy;
                asm volatile("atom.release.gpu.global.exch.b32 %0, [%1], %2;"
                             : "=r"(dummy) : "l"(myflag), "r"(base + step + 1)
                             : "memory");
            }
        }

#pragma unroll
        for (int r = 0; r < 5; r++) {
            int row = row0 + rg * 5 + r;
            Xout[((size_t)row * Lc + tin) * 256 + dir * H + col] = hval[r];
        }
    }
}

// ---------------------------------------------------------------------------
// Kernel 4: aggregation
// ---------------------------------------------------------------------------
__global__ __launch_bounds__(256) void agg_kernel(const float* __restrict__ X)
{
    int n = blockIdx.x, f = threadIdx.x;
    const float* base = X + (size_t)n * Lc * 256 + f;
    float s = 0.0f, m = -1e30f;
#pragma unroll 5
    for (int l = 0; l < Lc; l++) {
        float v = base[(size_t)l * 256];
        s += v; m = fmaxf(m, v);
    }
    g_agg[(size_t)n * 768 + f]       = s * (1.0f / Lc);
    g_agg[(size_t)n * 768 + 256 + f] = m;
    g_agg[(size_t)n * 768 + 512 + f] = (f < H) ? base[(Lc - 1) * 256] : base[0];
}

// ---------------------------------------------------------------------------
// Kernel 5: LayerNorm(512) + ReLU
// ---------------------------------------------------------------------------
__global__ __launch_bounds__(256) void ln_relu(
    const float* __restrict__ x, float* __restrict__ y,
    const float* __restrict__ gam, const float* __restrict__ bet)
{
    int row = blockIdx.x, tid = threadIdx.x;
    const float* xr = x + (size_t)row * 512;
    float v0 = xr[tid], v1 = xr[tid + 256];
    float s = v0 + v1, q = v0 * v0 + v1 * v1;
    __shared__ float ss[8], sq[8];
#pragma unroll
    for (int o = 16; o > 0; o >>= 1) {
        s += __shfl_down_sync(~0u, s, o);
        q += __shfl_down_sync(~0u, q, o);
    }
    int w = tid >> 5;
    if ((tid & 31) == 0) { ss[w] = s; sq[w] = q; }
    __syncthreads();
    if (tid == 0) {
        float S = 0.0f, Q = 0.0f;
        for (int i = 0; i < 8; i++) { S += ss[i]; Q += sq[i]; }
        ss[0] = S; sq[0] = Q;
    }
    __syncthreads();
    float mu  = ss[0] * (1.0f / 512.0f);
    float var = sq[0] * (1.0f / 512.0f) - mu * mu;
    float rs  = rsqrtf(var + 1e-5f);
    y[(size_t)row * 512 + tid]       = fmaxf((v0 - mu) * rs * gam[tid]       + bet[tid],       0.0f);
    y[(size_t)row * 512 + tid + 256] = fmaxf((v1 - mu) * rs * gam[tid + 256] + bet[tid + 256], 0.0f);
}

// ---------------------------------------------------------------------------
// Host orchestration
// ---------------------------------------------------------------------------
extern "C" void kernel_launch(void* const* d_in, const int* in_sizes, int n_in,
                              void* d_out, int out_size)
{
    const float* imu   = (const float*)d_in[0];
    const float* W_in  = (const float*)d_in[1];
    const float* b_in  = (const float*)d_in[2];
    const float* Wih[3] = {(const float*)d_in[3],  (const float*)d_in[7],  (const float*)d_in[11]};
    const float* Whh[3] = {(const float*)d_in[4],  (const float*)d_in[8],  (const float*)d_in[12]};
    const float* bih[3] = {(const float*)d_in[5],  (const float*)d_in[9],  (const float*)d_in[13]};
    const float* bhh[3] = {(const float*)d_in[6],  (const float*)d_in[10], (const float*)d_in[14]};
    const float* Wout1 = (const float*)d_in[15];
    const float* bout1 = (const float*)d_in[16];
    const float* ln_g  = (const float*)d_in[17];
    const float* ln_b  = (const float*)d_in[18];
    const float* Wout2 = (const float*)d_in[19];
    const float* bout2 = (const float*)d_in[20];
    float* out = (float*)d_out;

    float *pX0, *pXa, *pXb, *pxg, *pagg, *pt1, *pt2;
    cudaGetSymbolAddress((void**)&pX0,  g_X0);
    cudaGetSymbolAddress((void**)&pXa,  g_Xa);
    cudaGetSymbolAddress((void**)&pXb,  g_Xb);
    cudaGetSymbolAddress((void**)&pxg,  g_xg);
    cudaGetSymbolAddress((void**)&pagg, g_agg);
    cudaGetSymbolAddress((void**)&pt1,  g_t1);
    cudaGetSymbolAddress((void**)&pt2,  g_t2);

    constexpr int LSTM_SMEM = 128 * 64 * 16 + 2 * 8 * 3 * 128 * 8;  // 180224
    cudaFuncSetAttribute(lstm_layer,
                         cudaFuncAttributeMaxDynamicSharedMemorySize, LSTM_SMEM);
    cudaFuncSetAttribute(tf32_gemm,
                         cudaFuncAttributeMaxDynamicSharedMemorySize, GEMM_SMEM);

    reset_flags<<<1, 128>>>();
    inproj_kernel<<<(NR * 64) / 256, 256>>>(imu, W_in, b_in);

    float* Xin  = pX0;
    int    Kin  = 64;
    float* Xout = pXa;
    for (int layer = 0; layer < 3; layer++) {
        // xg = Xin @ Wih[dir] + (bih+bhh), both dirs fused in grid.x
        tf32_gemm<<<dim3(8, NR / 128), 256, GEMM_SMEM>>>(
            Xin, Wih[layer], pxg, bih[layer], bhh[layer],
            NR, G4, Kin,
            (long long)Kin * G4, (long long)NR * G4, (long long)G4, 4);
        lstm_layer<<<128, 512, LSTM_SMEM>>>(Whh[layer], pxg, Xout, layer);
        Xin = Xout;
        Kin = 256;
        Xout = (Xin == pXa) ? pXb : pXa;
    }
    float* Xfinal = Xin;

    agg_kernel<<<NSEQ, 256>>>(Xfinal);
    tf32_gemm<<<dim3(4, NSEQ / 128), 256, GEMM_SMEM>>>(
        pagg, Wout1, pt1, bout1, nullptr, NSEQ, 512, 768, 0, 0, 0, 4);
    ln_relu<<<NSEQ, 256>>>(pt1, pt2, ln_g, ln_b);
    tf32_gemm<<<dim3(2, NSEQ / 128), 256, GEMM_SMEM>>>(
        pt2, Wout2, out, bout2, nullptr, NSEQ, 256, 512, 0, 0, 0, 2);
}

// round 8
// speedup vs baseline: 2.2620x; 1.0576x over previous
#include <cuda_runtime.h>
#include <math.h>
#include <stdint.h>

// Problem constants
constexpr int Lc    = 50;
constexpr int NSEQ  = 32 * 40;     // 1280 sequences
constexpr int NR    = NSEQ * Lc;   // 64000 (seq,time) rows
constexpr int H     = 128;
constexpr int G4    = 512;         // 4*H gates

// ---------------------------------------------------------------------------
// Device scratch
// ---------------------------------------------------------------------------
__device__ float g_X0[(size_t)NR * 64];
__device__ float g_Xa[(size_t)NR * 256];
__device__ float g_Xb[(size_t)NR * 256];
__device__ float g_xg[2][(size_t)NR * G4];   // t-major: [dir][t][seq][512]
__device__ float g_hbuf[2][2][NSEQ * H];     // [step parity][dir][row*H+col]
__device__ int   g_flags[2][2][32][8];       // [dir][jtile][rowgroup][rg]
__device__ float g_agg[(size_t)NSEQ * 768];
__device__ float g_t1[(size_t)NSEQ * 512];
__device__ float g_t2[(size_t)NSEQ * 512];

// ---------------------------------------------------------------------------
// helpers
// ---------------------------------------------------------------------------
__device__ __forceinline__ float2 ffma2(float2 a, float2 b, float2 c) {
    unsigned long long ud;
    asm("fma.rn.f32x2 %0, %1, %2, %3;"
        : "=l"(ud)
        : "l"(*(unsigned long long*)&a),
          "l"(*(unsigned long long*)&b),
          "l"(*(unsigned long long*)&c));
    float2 d; *(unsigned long long*)&d = ud; return d;
}
__device__ __forceinline__ float2 pack2(float lo, float hi) {
    float2 r; r.x = lo; r.y = hi; return r;
}
__device__ __forceinline__ float sigm_(float x) {
    return __fdividef(1.0f, 1.0f + __expf(-x));
}
__device__ __forceinline__ float tanh_(float x) {
    return __fdividef(2.0f, 1.0f + __expf(-2.0f * x)) - 1.0f;
}
__device__ __forceinline__ uint32_t f2tf(float x) {
    uint32_t r;
    asm("cvt.rna.tf32.f32 %0, %1;" : "=r"(r) : "f"(x));
    return r;
}
__device__ __forceinline__ void mma_tf32(float* d, const uint32_t* a,
                                         const uint32_t* b) {
    asm volatile(
        "mma.sync.aligned.m16n8k8.row.col.f32.tf32.tf32.f32 "
        "{%0,%1,%2,%3}, {%4,%5,%6,%7}, {%8,%9}, {%0,%1,%2,%3};\n"
        : "+f"(d[0]), "+f"(d[1]), "+f"(d[2]), "+f"(d[3])
        : "r"(a[0]), "r"(a[1]), "r"(a[2]), "r"(a[3]), "r"(b[0]), "r"(b[1]));
}

// ---------------------------------------------------------------------------
// reset pairwise-sync flags (once per replay)
// ---------------------------------------------------------------------------
__global__ void reset_flags() {
    ((int*)g_flags)[threadIdx.x] = 0;
}

// ---------------------------------------------------------------------------
// Kernel 1: input projection
// ---------------------------------------------------------------------------
__global__ __launch_bounds__(256) void inproj_kernel(
    const float* __restrict__ imu, const float* __restrict__ Win,
    const float* __restrict__ bin)
{
    int idx = blockIdx.x * 256 + threadIdx.x;
    int row = idx >> 6;
    int jj  = idx & 63;
    int l   = row % Lc;
    const float* xr = imu + (size_t)row * 6;
    float t    = (float)l * (1.0f / 49.0f);
    float rate = 1.0f;
    float acc = bin[jj];
#pragma unroll
    for (int k = 0; k < 6; k++) acc = fmaf(xr[k], Win[k * 64 + jj], acc);
    acc = fmaf(t,    Win[6 * 64 + jj], acc);
    acc = fmaf(rate, Win[7 * 64 + jj], acc);
    g_X0[(size_t)row * 64 + jj] = fmaxf(acc, 0.0f);
}

// ---------------------------------------------------------------------------
// Kernel 2: tf32 tensor-core GEMM + bias. Optional t-major output permutation
// (permute != 0): out_row = (row % Lc)*NSEQ + row/Lc.
// ---------------------------------------------------------------------------
constexpr int APITCH = 132;
constexpr int BPITCH = 260;
constexpr int ASZ = 4 * 8 * APITCH;
constexpr int BSZ = 4 * 4 * BPITCH;
constexpr int GEMM_SMEM = (2 * ASZ + 2 * BSZ) * 4;

__device__ __forceinline__ int asI(int buf, int ks, int c, int q) {
    return ((buf * 4 + ks) * 8 + c) * APITCH + q;
}
__device__ __forceinline__ int bsI(int buf, int ks, int kp, int q) {
    return ((buf * 4 + ks) * 4 + kp) * BPITCH + q;
}

__global__ __launch_bounds__(256) void tf32_gemm(
    const float* __restrict__ A, const float* __restrict__ B,
    float* __restrict__ C,
    const float* __restrict__ bias1, const float* __restrict__ bias2,
    int M, int N, int K,
    long long sB, long long sC, long long sBias, int nbx, int permute)
{
    extern __shared__ uint32_t sm[];
    uint32_t* As = sm;
    uint32_t* Bs = sm + 2 * ASZ;

    const int dir = blockIdx.x / nbx;
    const int nb  = blockIdx.x % nbx;
    const int mb  = blockIdx.y;
    B += (size_t)dir * sB;
    C += (size_t)dir * sC;
    const float* b1 = bias1 + (size_t)dir * sBias;
    const float* b2 = bias2 ? bias2 + (size_t)dir * sBias : nullptr;
    const bool hasB2 = (b2 != nullptr);

    const int tid  = threadIdx.x;
    const int warp = tid >> 5, lane = tid & 31;
    const int wR = warp >> 2, wC = warp & 3;
    const int g  = lane >> 2, tig = lane & 3;

    const float* Ab = A + (size_t)(mb * 128) * K;
    const float* Bb = B + nb * 128;

    const int lr  = tid >> 3;
    const int lc4 = (tid & 7) * 4;
    const int aks = lc4 >> 3, ac0 = lc4 & 7;
    const int bks = lr >> 3, br8 = lr & 7;
    const int bkp = br8 & 3, bhalf = br8 >> 2;

    float acc[4][4][4];
#pragma unroll
    for (int mt = 0; mt < 4; mt++)
#pragma unroll
        for (int nt = 0; nt < 4; nt++)
#pragma unroll
            for (int q = 0; q < 4; q++) acc[mt][nt][q] = 0.0f;

    const int niter = K / 32;

    {
#pragma unroll
        for (int i = 0; i < 4; i++) {
            int r = lr + i * 32;
            float4 v = *(const float4*)(Ab + (size_t)r * K + lc4);
            int q = ((r >> 4) << 4) + ((r & 7) << 1) + ((r >> 3) & 1);
            uint32_t* d = &As[asI(0, aks, ac0, q)];
            d[0] = f2tf(v.x); d[APITCH] = f2tf(v.y);
            d[2 * APITCH] = f2tf(v.z); d[3 * APITCH] = f2tf(v.w);
        }
#pragma unroll
        for (int i = 0; i < 4; i++) {
            int col = lc4 + i * 32;
            float4 v = *(const float4*)(Bb + (size_t)lr * N + col);
            uint32_t* d = &Bs[bsI(0, bks, bkp, col * 2 + bhalf)];
            d[0] = f2tf(v.x); d[2] = f2tf(v.y);
            d[4] = f2tf(v.z); d[6] = f2tf(v.w);
        }
    }
    __syncthreads();

    for (int it = 0; it < niter; it++) {
        const int cur = it & 1, nxt = cur ^ 1;
        const bool more = (it + 1 < niter);
        float4 av[4], bv[4];
        if (more) {
            int k0 = (it + 1) * 32;
#pragma unroll
            for (int i = 0; i < 4; i++) {
                av[i] = *(const float4*)(Ab + (size_t)(lr + i * 32) * K + k0 + lc4);
                bv[i] = *(const float4*)(Bb + (size_t)(k0 + lr) * N + lc4 + i * 32);
            }
        }

#pragma unroll
        for (int ks = 0; ks < 4; ks++) {
            uint32_t af[4][4];
#pragma unroll
            for (int mt = 0; mt < 4; mt++) {
                int q = ((wR * 4 + mt) << 4) + (g << 1);
                uint2 u0 = *(const uint2*)&As[asI(cur, ks, tig, q)];
                uint2 u1 = *(const uint2*)&As[asI(cur, ks, tig + 4, q)];
                af[mt][0] = u0.x; af[mt][1] = u0.y;
                af[mt][2] = u1.x; af[mt][3] = u1.y;
            }
            uint32_t bf[4][2];
#pragma unroll
            for (int nt = 0; nt < 4; nt++) {
                int n = wC * 32 + nt * 8 + g;
                uint2 u = *(const uint2*)&Bs[bsI(cur, ks, tig, n * 2)];
                bf[nt][0] = u.x; bf[nt][1] = u.y;
            }
#pragma unroll
            for (int mt = 0; mt < 4; mt++)
#pragma unroll
                for (int nt = 0; nt < 4; nt++)
                    mma_tf32(acc[mt][nt], af[mt], bf[nt]);
        }

        if (more) {
#pragma unroll
            for (int i = 0; i < 4; i++) {
                int r = lr + i * 32;
                int q = ((r >> 4) << 4) + ((r & 7) << 1) + ((r >> 3) & 1);
                uint32_t* d = &As[asI(nxt, aks, ac0, q)];
                d[0] = f2tf(av[i].x); d[APITCH] = f2tf(av[i].y);
                d[2 * APITCH] = f2tf(av[i].z); d[3 * APITCH] = f2tf(av[i].w);
                int col = lc4 + i * 32;
                uint32_t* db = &Bs[bsI(nxt, bks, bkp, col * 2 + bhalf)];
                db[0] = f2tf(bv[i].x); db[2] = f2tf(bv[i].y);
                db[4] = f2tf(bv[i].z); db[6] = f2tf(bv[i].w);
            }
        }
        __syncthreads();
    }

#pragma unroll
    for (int mt = 0; mt < 4; mt++) {
        int rowa = mb * 128 + wR * 64 + mt * 16 + g;
        int rowb = rowa + 8;
        size_t ra = permute ? ((size_t)(rowa % Lc) * NSEQ + rowa / Lc) : (size_t)rowa;
        size_t rb = permute ? ((size_t)(rowb % Lc) * NSEQ + rowb / Lc) : (size_t)rowb;
#pragma unroll
        for (int nt = 0; nt < 4; nt++) {
            int colg = nb * 128 + wC * 32 + nt * 8 + 2 * tig;
            float bx = b1[colg], by = b1[colg + 1];
            if (hasB2) { bx += b2[colg]; by += b2[colg + 1]; }
            float2 v0 = pack2(acc[mt][nt][0] + bx, acc[mt][nt][1] + by);
            float2 v1 = pack2(acc[mt][nt][2] + bx, acc[mt][nt][3] + by);
            *(float2*)(C + ra * N + colg) = v0;
            *(float2*)(C + rb * N + colg) = v1;
        }
    }
}

// ---------------------------------------------------------------------------
// Kernel 3: PERSISTENT BiLSTM layer, warp-pair decoupled.
// 128 CTAs x 512 threads. CTA = (dir, jt, rowgroup of 40 rows).
// warp = (rg 0..7, jh 0..1); rg pair (2 warps, 64 threads) owns 5 rows and
// synchronizes ONLY with: its sibling warp (named barrier id=rg) and the
// partner CTA's same-rg pair (per-rg release/acquire flag). No __syncthreads
// in the step loop — independent chains slip freely.
// ---------------------------------------------------------------------------
#define BARRG(rgid) asm volatile("bar.sync %0, 64;" :: "r"(rgid) : "memory")

__global__ __launch_bounds__(512) void lstm_layer(
    const float* __restrict__ Whh,
    const float* __restrict__ xgb,   // t-major [dir][t][seq][512]
    float* __restrict__ Xout,
    int layer)
{
    extern __shared__ float smem[];
    float4* ws  = (float4*)smem;                 // [128][64] gate quads
    float*  hsf = smem + 128 * 64 * 4;
    constexpr int RGSZ = 3 * 128 * 2;            // floats per rg slice
    constexpr int HBUF = 8 * RGSZ;               // floats per buffer

    const int bx   = blockIdx.x;
    const int dir  = bx >> 6;
    const int jt   = (bx >> 5) & 1;
    const int rgI  = bx & 31;
    const int row0 = rgI * 40;
    const int tid  = threadIdx.x;
    const int warp = tid >> 5, lane = tid & 31;
    const int rg   = warp >> 1, jh = warp & 1;
    const int jcol = (jh << 5) + lane;           // 0..63
    const int col  = (jt << 6) + jcol;           // 0..127
    const int rbase = row0 + rg * 5;
    const int base = layer * Lc;
    const bool leader = (jh == 0 && lane == 0);

    const float* W   = Whh + (size_t)dir * (H * G4);
    const float* xgd = xgb + (size_t)dir * NR * G4;
    int* myflag = &g_flags[dir][jt][rgI][rg];
    int* pflag  = &g_flags[dir][jt ^ 1][rgI][rg];

    for (int idx = tid; idx < 128 * 64; idx += 512) {
        int k = idx >> 6, j = idx & 63;
        const float* wk = W + (size_t)k * G4 + (jt << 6) + j;
        ws[idx] = make_float4(wk[0], wk[128], wk[256], wk[384]);
    }
    __syncthreads();

    float c[5];
#pragma unroll
    for (int r = 0; r < 5; r++) c[r] = 0.0f;

    for (int step = 0; step < Lc; step++) {
        const int tin = dir ? (Lc - 1 - step) : step;

        // xg loads (t-major: contiguous region per step)
        float2 acc2[4][2];
        float  accs[4];
        const float* xp = xgd + ((size_t)tin * NSEQ + rbase) * G4 + col;
#pragma unroll
        for (int p = 0; p < 2; p++) {
            const float* xa = xp + (size_t)(2 * p) * G4;
            const float* xb = xa + G4;
#pragma unroll
            for (int gi = 0; gi < 4; gi++)
                acc2[gi][p] = pack2(xa[gi * 128], xb[gi * 128]);
        }
        {
            const float* xa = xp + (size_t)4 * G4;
#pragma unroll
            for (int gi = 0; gi < 4; gi++) accs[gi] = xa[gi * 128];
        }

        if (step > 0) {
            if (leader) {
                const int want = base + step;
                int v;
                do {
                    asm volatile("ld.acquire.gpu.global.b32 %0, [%1];"
                                 : "=r"(v) : "l"(pflag) : "memory");
                } while (v < want);
            }
            BARRG(rg);

            // restage partner half (this rg's 5 rows, this warp's 32 cols)
            {
                const float* hbg = g_hbuf[(step + 1) & 1][dir];
                float* hc = hsf + ((step + 1) & 1) * HBUF + rg * RGSZ;
                int pc = ((jt ^ 1) << 6) + jcol;
#pragma unroll
                for (int r = 0; r < 5; r++)
                    hc[(((r >> 1) << 7) + pc) * 2 + (r & 1)] =
                        hbg[(size_t)(rbase + r) * H + pc];
            }
            BARRG(rg);

            // k-loop
            const float*  hrow  = hsf + ((step + 1) & 1) * HBUF + rg * RGSZ;
            const float2* hrow2 = (const float2*)hrow;
#pragma unroll 8
            for (int k = 0; k < 128; k++) {
                float4 w4 = ws[(k << 6) + jcol];
                float2 ha = hrow2[k];
                float2 hb = hrow2[128 + k];
                float  hc = hrow[(256 + k) * 2];
                float2 w0 = pack2(w4.x, w4.x);
                float2 w1 = pack2(w4.y, w4.y);
                float2 w2 = pack2(w4.z, w4.z);
                float2 w3 = pack2(w4.w, w4.w);
                acc2[0][0] = ffma2(ha, w0, acc2[0][0]);
                acc2[1][0] = ffma2(ha, w1, acc2[1][0]);
                acc2[2][0] = ffma2(ha, w2, acc2[2][0]);
                acc2[3][0] = ffma2(ha, w3, acc2[3][0]);
                acc2[0][1] = ffma2(hb, w0, acc2[0][1]);
                acc2[1][1] = ffma2(hb, w1, acc2[1][1]);
                acc2[2][1] = ffma2(hb, w2, acc2[2][1]);
                acc2[3][1] = ffma2(hb, w3, acc2[3][1]);
                accs[0] = fmaf(hc, w4.x, accs[0]);
                accs[1] = fmaf(hc, w4.y, accs[1]);
                accs[2] = fmaf(hc, w4.z, accs[2]);
                accs[3] = fmaf(hc, w4.w, accs[3]);
            }
        }

        // gates + state update
        float hval[5];
#pragma unroll
        for (int p = 0; p < 2; p++) {
            float i0 = sigm_(acc2[0][p].x), i1 = sigm_(acc2[0][p].y);
            float f0 = sigm_(acc2[1][p].x), f1 = sigm_(acc2[1][p].y);
            float ga = tanh_(acc2[2][p].x), gb = tanh_(acc2[2][p].y);
            float o0 = sigm_(acc2[3][p].x), o1 = sigm_(acc2[3][p].y);
            float c0 = fmaf(f0, c[2 * p],     i0 * ga);
            float c1 = fmaf(f1, c[2 * p + 1], i1 * gb);
            c[2 * p] = c0; c[2 * p + 1] = c1;
            hval[2 * p]     = o0 * tanh_(c0);
            hval[2 * p + 1] = o1 * tanh_(c1);
        }
        {
            float ig = sigm_(accs[0]);
            float fg = sigm_(accs[1]);
            float gg = tanh_(accs[2]);
            float og = sigm_(accs[3]);
            float cn = fmaf(fg, c[4], ig * gg);
            c[4] = cn;
            hval[4] = og * tanh_(cn);
        }

        // publish own half: local smem + global for partner, then flag
        if (step < Lc - 1) {
            float* hw  = hsf + (step & 1) * HBUF + rg * RGSZ;
            float* hbw = g_hbuf[step & 1][dir];
#pragma unroll
            for (int r = 0; r < 5; r++) {
                hw[(((r >> 1) << 7) + col) * 2 + (r & 1)] = hval[r];
                hbw[(size_t)(rbase + r) * H + col] = hval[r];
            }
            BARRG(rg);
            if (leader) {
                int dummy;
                asm volatile("atom.release.gpu.global.exch.b32 %0, [%1], %2;"
                             : "=r"(dummy) : "l"(myflag), "r"(base + step + 1)
                             : "memory");
            }
        }

        // layer output
#pragma unroll
        for (int r = 0; r < 5; r++)
            Xout[((size_t)(rbase + r) * Lc + tin) * 256 + dir * H + col] = hval[r];
    }
}

// ---------------------------------------------------------------------------
// Kernel 4: aggregation
// ---------------------------------------------------------------------------
__global__ __launch_bounds__(256) void agg_kernel(const float* __restrict__ X)
{
    int n = blockIdx.x, f = threadIdx.x;
    const float* base = X + (size_t)n * Lc * 256 + f;
    float s = 0.0f, m = -1e30f;
#pragma unroll 5
    for (int l = 0; l < Lc; l++) {
        float v = base[(size_t)l * 256];
        s += v; m = fmaxf(m, v);
    }
    g_agg[(size_t)n * 768 + f]       = s * (1.0f / Lc);
    g_agg[(size_t)n * 768 + 256 + f] = m;
    g_agg[(size_t)n * 768 + 512 + f] = (f < H) ? base[(Lc - 1) * 256] : base[0];
}

// ---------------------------------------------------------------------------
// Kernel 5: LayerNorm(512) + ReLU
// ---------------------------------------------------------------------------
__global__ __launch_bounds__(256) void ln_relu(
    const float* __restrict__ x, float* __restrict__ y,
    const float* __restrict__ gam, const float* __restrict__ bet)
{
    int row = blockIdx.x, tid = threadIdx.x;
    const float* xr = x + (size_t)row * 512;
    float v0 = xr[tid], v1 = xr[tid + 256];
    float s = v0 + v1, q = v0 * v0 + v1 * v1;
    __shared__ float ss[8], sq[8];
#pragma unroll
    for (int o = 16; o > 0; o >>= 1) {
        s += __shfl_down_sync(~0u, s, o);
        q += __shfl_down_sync(~0u, q, o);
    }
    int w = tid >> 5;
    if ((tid & 31) == 0) { ss[w] = s; sq[w] = q; }
    __syncthreads();
    if (tid == 0) {
        float S = 0.0f, Q = 0.0f;
        for (int i = 0; i < 8; i++) { S += ss[i]; Q += sq[i]; }
        ss[0] = S; sq[0] = Q;
    }
    __syncthreads();
    float mu  = ss[0] * (1.0f / 512.0f);
    float var = sq[0] * (1.0f / 512.0f) - mu * mu;
    float rs  = rsqrtf(var + 1e-5f);
    y[(size_t)row * 512 + tid]       = fmaxf((v0 - mu) * rs * gam[tid]       + bet[tid],       0.0f);
    y[(size_t)row * 512 + tid + 256] = fmaxf((v1 - mu) * rs * gam[tid + 256] + bet[tid + 256], 0.0f);
}

// ---------------------------------------------------------------------------
// Host orchestration
// ---------------------------------------------------------------------------
extern "C" void kernel_launch(void* const* d_in, const int* in_sizes, int n_in,
                              void* d_out, int out_size)
{
    const float* imu   = (const float*)d_in[0];
    const float* W_in  = (const float*)d_in[1];
    const float* b_in  = (const float*)d_in[2];
    const float* Wih[3] = {(const float*)d_in[3],  (const float*)d_in[7],  (const float*)d_in[11]};
    const float* Whh[3] = {(const float*)d_in[4],  (const float*)d_in[8],  (const float*)d_in[12]};
    const float* bih[3] = {(const float*)d_in[5],  (const float*)d_in[9],  (const float*)d_in[13]};
    const float* bhh[3] = {(const float*)d_in[6],  (const float*)d_in[10], (const float*)d_in[14]};
    const float* Wout1 = (const float*)d_in[15];
    const float* bout1 = (const float*)d_in[16];
    const float* ln_g  = (const float*)d_in[17];
    const float* ln_b  = (const float*)d_in[18];
    const float* Wout2 = (const float*)d_in[19];
    const float* bout2 = (const float*)d_in[20];
    float* out = (float*)d_out;

    float *pX0, *pXa, *pXb, *pxg, *pagg, *pt1, *pt2;
    cudaGetSymbolAddress((void**)&pX0,  g_X0);
    cudaGetSymbolAddress((void**)&pXa,  g_Xa);
    cudaGetSymbolAddress((void**)&pXb,  g_Xb);
    cudaGetSymbolAddress((void**)&pxg,  g_xg);
    cudaGetSymbolAddress((void**)&pagg, g_agg);
    cudaGetSymbolAddress((void**)&pt1,  g_t1);
    cudaGetSymbolAddress((void**)&pt2,  g_t2);

    constexpr int LSTM_SMEM = 128 * 64 * 16 + 2 * 8 * 3 * 128 * 8;  // 180224
    cudaFuncSetAttribute(lstm_layer,
                         cudaFuncAttributeMaxDynamicSharedMemorySize, LSTM_SMEM);
    cudaFuncSetAttribute(tf32_gemm,
                         cudaFuncAttributeMaxDynamicSharedMemorySize, GEMM_SMEM);

    reset_flags<<<1, 1024>>>();
    inproj_kernel<<<(NR * 64) / 256, 256>>>(imu, W_in, b_in);

    float* Xin  = pX0;
    int    Kin  = 64;
    float* Xout = pXa;
    for (int layer = 0; layer < 3; layer++) {
        // xg = Xin @ Wih[dir] + (bih+bhh); output permuted to t-major
        tf32_gemm<<<dim3(8, NR / 128), 256, GEMM_SMEM>>>(
            Xin, Wih[layer], pxg, bih[layer], bhh[layer],
            NR, G4, Kin,
            (long long)Kin * G4, (long long)NR * G4, (long long)G4, 4, 1);
        lstm_layer<<<128, 512, LSTM_SMEM>>>(Whh[layer], pxg, Xout, layer);
        Xin = Xout;
        Kin = 256;
        Xout = (Xin == pXa) ? pXb : pXa;
    }
    float* Xfinal = Xin;

    agg_kernel<<<NSEQ, 256>>>(Xfinal);
    tf32_gemm<<<dim3(4, NSEQ / 128), 256, GEMM_SMEM>>>(
        pagg, Wout1, pt1, bout1, nullptr, NSEQ, 512, 768, 0, 0, 0, 4, 0);
    ln_relu<<<NSEQ, 256>>>(pt1, pt2, ln_g, ln_b);
    tf32_gemm<<<dim3(2, NSEQ / 128), 256, GEMM_SMEM>>>(
        pt2, Wout2, out, bout2, nullptr, NSEQ, 256, 512, 0, 0, 0, 2, 0);
}